// round 17
// baseline (speedup 1.0000x reference)
#include <cuda_runtime.h>
#include <cuda_fp16.h>

#define NT 384
#define EARB 144           // EA staging row stride (fp32, padded)
#define PRB  272           // P staging row stride
#define WPB  11264         // per-warp staging stride

// ---- edge-kernel smem layout ----
#define OFF_SC 0           // scale,shift,b1,b3 = 2048
#define OFF_W1 2048        // 8192  (1 kstep-pair, uint4 frags)
#define OFF_W2 10240       // 32768 (W2c2: 4 pairs)
#define OFF_W3 43008       // 32768 (W3: 4 pairs)
#define OFF_WP 75776       // 12 warps x 11264 (EA 2304 | PR 4352 | PC 4352)
#define SMEM_E (75776 + 12 * 11264)

// ---- node-kernel smem layout (double-buffered A) ----
#define ARB  272
#define NOFF_W   0         // 65536
#define NOFF_A0  65536     // 34816
#define NOFF_A1  100352    // 34816
#define SMEM_N   135168

__device__ __align__(16) unsigned g_P[131072 * 128];
// paired fragment scratch for edge kernel (uint4 = ksteps 2p, 2p+1)
__device__ __align__(16) uint4 g_W1p[512];
__device__ __align__(16) uint4 g_W2c2p[4 * 512];
__device__ __align__(16) uint4 g_W3p[4 * 512];

#define CP16(dst, src)  asm volatile("cp.async.cg.shared.global [%0], [%1], 16;" :: "r"(dst), "l"(src) : "memory")
#define CP_COMMIT()     asm volatile("cp.async.commit_group;" ::: "memory")
#define CP_WAIT(n)      asm volatile("cp.async.wait_group %0;" :: "n"(n) : "memory")

__device__ __forceinline__ unsigned smem_u32(const void* p) {
    unsigned a;
    asm("{ .reg .u64 t; cvta.to.shared.u64 t, %1; cvt.u32.u64 %0, t; }" : "=r"(a) : "l"(p));
    return a;
}
__device__ __forceinline__ unsigned f22h2(float lo, float hi) {
    unsigned r;
    asm("cvt.rn.f16x2.f32 %0, %1, %2;" : "=r"(r) : "f"(hi), "f"(lo));
    return r;
}
__device__ __forceinline__ float2 h2f2(unsigned u) {
    __half2 h; *(unsigned*)&h = u;
    return __half22float2(h);
}
__device__ __forceinline__ void mma16(float* c, unsigned a0, unsigned a1, unsigned a2,
                                      unsigned a3, unsigned b0, unsigned b1) {
    asm volatile("mma.sync.aligned.m16n8k16.row.col.f32.f16.f16.f32 "
        "{%0,%1,%2,%3}, {%4,%5,%6,%7}, {%8,%9}, {%0,%1,%2,%3};"
        : "+f"(c[0]), "+f"(c[1]), "+f"(c[2]), "+f"(c[3])
        : "r"(a0), "r"(a1), "r"(a2), "r"(a3), "r"(b0), "r"(b1));
}
__device__ __forceinline__ float tanh_mufu(float v) {
    float r;
    asm("tanh.approx.f32 %0, %1;" : "=f"(r) : "f"(v));
    return r;
}
__device__ __forceinline__ void st_cs_v2(float* p, float a, float b) {
    asm volatile("st.global.cs.v2.f32 [%0], {%1,%2};" :: "l"(p), "f"(a), "f"(b) : "memory");
}

// fragment for (W, lane, nt, cq, kstep): uint2 of fp16x2
__device__ __forceinline__ uint2 mk_frag(const float* W, int lane, int nt, int cq, int ks) {
    int n = cq * 32 + nt * 8 + (lane >> 2), k0 = ks * 16 + (lane & 3) * 2;
    return make_uint2(f22h2(W[k0 * 128 + n], W[(k0 + 1) * 128 + n]),
                      f22h2(W[(k0 + 8) * 128 + n], W[(k0 + 9) * 128 + n]));
}

// ---- node projections: persistent, double-buffered pipeline ----
__global__ void __launch_bounds__(512, 1)
node_proj(const float* __restrict__ x, const float* __restrict__ W1,
          const float* __restrict__ W2, const float* __restrict__ W3,
          int N, int ntilesN) {
    extern __shared__ char smem[];
    const int tid = threadIdx.x;
    const int w = tid >> 5, lane = tid & 31;
    const int gid = lane >> 2, tig = lane & 3;
    const int rb = (w >> 2) * 32, cq = w & 3, cbase = cq * 32;
    const int r4 = tid >> 2, q4 = tid & 3;

    // compute own W2 c0+c1 frags (ksteps 0..15) into smem
    for (int i = tid; i < 16 * 512; i += 512) {
        int l = i & 31, nt = (i >> 5) & 3, c = (i >> 7) & 3, ks = i >> 9;
        *(uint2*)(smem + NOFF_W + i * 8) = mk_frag(W2, l, nt, c, ks);
    }
    // block 0 writes paired global frags for the edge kernel
    if (blockIdx.x == 0) {
        for (int j = tid; j < 512; j += 512) {
            int l = j & 31, nt = (j >> 5) & 3, c = (j >> 7) & 3;
            uint2 f0 = mk_frag(W1, l, nt, c, 0), f1 = mk_frag(W1, l, nt, c, 1);
            g_W1p[j] = make_uint4(f0.x, f0.y, f1.x, f1.y);
        }
        for (int j = tid; j < 2048; j += 512) {
            int l = j & 31, nt = (j >> 5) & 3, c = (j >> 7) & 3, p = j >> 9;
            uint2 f0 = mk_frag(W2, l, nt, c, 16 + 2 * p);
            uint2 f1 = mk_frag(W2, l, nt, c, 16 + 2 * p + 1);
            g_W2c2p[j] = make_uint4(f0.x, f0.y, f1.x, f1.y);
        }
        for (int j = tid; j < 2048; j += 512) {
            int l = j & 31, nt = (j >> 5) & 3, c = (j >> 7) & 3, p = j >> 9;
            uint2 f0 = mk_frag(W3, l, nt, c, 2 * p), f1 = mk_frag(W3, l, nt, c, 2 * p + 1);
            g_W3p[j] = make_uint4(f0.x, f0.y, f1.x, f1.y);
        }
    }
    __syncthreads();

    const uint2* Wt = (const uint2*)(smem + NOFF_W) + cq * 128 + lane;

    #define LDGX(tile) { \
        int _node = min((tile) * 128 + r4, N - 1); \
        const float4* _s = (const float4*)(x + (long long)_node * 128 + q4 * 32); \
        _Pragma("unroll") for (int _i = 0; _i < 8; _i++) xr[_i] = __ldg(_s + _i); }

    float4 xr[8];
    int tile = blockIdx.x;
    if (tile < ntilesN) LDGX(tile);
    int pp = 0;

    for (; tile < ntilesN; tile += gridDim.x) {
        char* A = smem + (pp ? NOFF_A1 : NOFF_A0);
        // cvt regs -> fp16 A buffer
        {
            unsigned* d = (unsigned*)(A + r4 * ARB) + q4 * 16;
            #pragma unroll
            for (int i = 0; i < 8; i++) {
                d[2 * i]     = f22h2(xr[i].x, xr[i].y);
                d[2 * i + 1] = f22h2(xr[i].z, xr[i].w);
            }
        }
        __syncthreads();
        // prefetch next tile under the GEMM
        int nt2 = tile + gridDim.x;
        if (nt2 < ntilesN) LDGX(nt2);

        const char* Ath = A + (rb + gid) * ARB + tig * 4;
        float acc[2][4][4];
        #pragma unroll
        for (int ch = 0; ch < 2; ch++) {
            #pragma unroll
            for (int m = 0; m < 2; m++)
                #pragma unroll
                for (int n = 0; n < 4; n++)
                    { acc[m][n][0]=0.f; acc[m][n][1]=0.f; acc[m][n][2]=0.f; acc[m][n][3]=0.f; }
            #pragma unroll
            for (int ks = 0; ks < 8; ks++) {
                unsigned a[2][4];
                #pragma unroll
                for (int mt = 0; mt < 2; mt++) {
                    const char* Am = Ath + ks * 32 + mt * 16 * ARB;
                    a[mt][0] = *(const unsigned*)(Am);
                    a[mt][1] = *(const unsigned*)(Am + 8 * ARB);
                    a[mt][2] = *(const unsigned*)(Am + 16);
                    a[mt][3] = *(const unsigned*)(Am + 8 * ARB + 16);
                }
                const uint2* Bk = Wt + (ch * 8 + ks) * 512;
                #pragma unroll
                for (int nt = 0; nt < 4; nt++) {
                    uint2 b = Bk[nt * 32];
                    mma16(acc[0][nt], a[0][0], a[0][1], a[0][2], a[0][3], b.x, b.y);
                    mma16(acc[1][nt], a[1][0], a[1][1], a[1][2], a[1][3], b.x, b.y);
                }
            }
            #pragma unroll
            for (int mt = 0; mt < 2; mt++) {
                int node0 = tile * 128 + rb + mt * 16 + gid;
                int pcol = ch * 64 + (cbase >> 1) + tig;
                #pragma unroll
                for (int nt = 0; nt < 4; nt++) {
                    if (node0 < N)
                        g_P[(long long)node0 * 128 + pcol + nt * 4] =
                            f22h2(acc[mt][nt][0], acc[mt][nt][1]);
                    if (node0 + 8 < N)
                        g_P[(long long)(node0 + 8) * 128 + pcol + nt * 4] =
                            f22h2(acc[mt][nt][2], acc[mt][nt][3]);
                }
            }
        }
        pp ^= 1;
    }
}

// ---- edge kernel: 12 warps, barrier-free per-warp streams, paired B-frag LDS.128 ----
// (byte-identical to round 16's measured 172.9us kernel)
__global__ void __launch_bounds__(NT, 1)
edge_kernel(const int* __restrict__ ei, const float* __restrict__ ea,
            const float* __restrict__ b1, const float* __restrict__ b2,
            const float* __restrict__ gamma, const float* __restrict__ beta,
            const float* __restrict__ mean, const float* __restrict__ var,
            const float* __restrict__ b3,
            float* __restrict__ out, int E, int nchunks)
{
    extern __shared__ char smem[];
    const unsigned sb = smem_u32(smem);
    float* sScale = (float*)(smem + OFF_SC);
    float* sShift = (float*)(smem + OFF_SC + 512);
    float* sB1    = (float*)(smem + OFF_SC + 1024);
    float* sB3    = (float*)(smem + OFF_SC + 1536);

    const int tid = threadIdx.x;
    const int w = tid >> 5, lane = tid & 31;
    const int gid = lane >> 2, tig = lane & 3;
    const int l16 = lane & 15, lh = lane >> 4;

    if (tid < 128) {
        float sc = gamma[tid] * rsqrtf(var[tid] + 1e-5f);
        sScale[tid] = sc;
        sShift[tid] = (b2[tid] - mean[tid]) * sc + beta[tid];
        sB1[tid] = b1[tid];
        sB3[tid] = b3[tid];
    }
    for (int i = tid; i < 512; i += NT)
        CP16(sb + OFF_W1 + i * 16, (const char*)g_W1p + i * 16);
    for (int i = tid; i < 2048; i += NT)
        CP16(sb + OFF_W2 + i * 16, (const char*)g_W2c2p + i * 16);
    for (int i = tid; i < 2048; i += NT)
        CP16(sb + OFF_W3 + i * 16, (const char*)g_W3p + i * 16);
    CP_COMMIT(); CP_WAIT(0);
    __syncthreads();

    const bool is64 = ((ei[1] | ei[3] | ei[5] | ei[7]) == 0);
    const long long* ei64 = (const long long*)ei;

    const unsigned wp = sb + OFF_WP + w * WPB;
    const unsigned sEA = wp;
    const unsigned sPR = wp + 2304;
    const unsigned sPC = wp + 6656;
    const uint4* W1t = (const uint4*)(smem + OFF_W1) + lane;
    const uint4* W2t = (const uint4*)(smem + OFF_W2) + lane;
    const uint4* W3t = (const uint4*)(smem + OFF_W3) + lane;

    #define LDIDX(dst, eb) { int _e = min((eb) + l16, E - 1); \
        long long _o = (lane < 16) ? (long long)_e : (long long)E + _e; \
        (dst) = is64 ? (int)ei64[_o] : ei[_o]; }
    #define ISSUE_EA(eb) { int _ge = min((eb) + l16, E - 1); \
        const float* _s = ea + (long long)_ge * 32 + lh * 16; \
        unsigned _d = sEA + l16 * EARB + lh * 64; \
        CP16(_d, _s); CP16(_d + 16, _s + 4); \
        CP16(_d + 32, _s + 8); CP16(_d + 48, _s + 12); CP_COMMIT(); }

    const int stride = gridDim.x * 12;
    const int c0 = blockIdx.x * 12 + w;

    int idxv;
    LDIDX(idxv, c0 * 16);
    ISSUE_EA(c0 * 16);

    float acc[16][4];
    unsigned ef[32];

    for (int c = c0; c < nchunks; c += stride) {
        const int ebase = c * 16;

        {
            int nR = __shfl_sync(0xffffffffu, idxv, l16);
            int nC = __shfl_sync(0xffffffffu, idxv, 16 + l16);
            const char* srcR = (const char*)g_P + (long long)nR * 512 + lh * 128;
            const char* srcC = (const char*)g_P + (long long)nC * 512 + 256 + lh * 128;
            unsigned dR = sPR + l16 * PRB + lh * 128;
            unsigned dC = sPC + l16 * PRB + lh * 128;
            #pragma unroll
            for (int i = 0; i < 8; i++) CP16(dR + i * 16, srcR + i * 16);
            #pragma unroll
            for (int i = 0; i < 8; i++) CP16(dC + i * 16, srcC + i * 16);
            CP_COMMIT();
        }
        CP_WAIT(1);
        __syncwarp();

        #pragma unroll
        for (int j = 0; j < 16; j++) { acc[j][0]=0.f; acc[j][1]=0.f; acc[j][2]=0.f; acc[j][3]=0.f; }
        {
            unsigned a[2][4];
            #pragma unroll
            for (int ks = 0; ks < 2; ks++) {
                const char* Ak = (const char*)smem + (sEA - sb) + ks * 64 + tig * 8;
                float2 v0 = *(const float2*)(Ak + gid * EARB);
                float2 v1 = *(const float2*)(Ak + (gid + 8) * EARB);
                float2 v2 = *(const float2*)(Ak + gid * EARB + 32);
                float2 v3 = *(const float2*)(Ak + (gid + 8) * EARB + 32);
                a[ks][0] = f22h2(v0.x, v0.y); a[ks][1] = f22h2(v1.x, v1.y);
                a[ks][2] = f22h2(v2.x, v2.y); a[ks][3] = f22h2(v3.x, v3.y);
            }
            #pragma unroll
            for (int blk = 0; blk < 16; blk++) {
                uint4 b = W1t[(blk >> 2) * 128 + (blk & 3) * 32];
                mma16(acc[blk], a[0][0], a[0][1], a[0][2], a[0][3], b.x, b.y);
                mma16(acc[blk], a[1][0], a[1][1], a[1][2], a[1][3], b.z, b.w);
            }
        }

        #pragma unroll
        for (int j = 0; j < 16; j++) {
            float2 bb = *(const float2*)(sB1 + j * 8 + 2 * tig);
            ef[2*j]   = f22h2(tanh_mufu(acc[j][0] + bb.x), tanh_mufu(acc[j][1] + bb.y));
            ef[2*j+1] = f22h2(tanh_mufu(acc[j][2] + bb.x), tanh_mufu(acc[j][3] + bb.y));
        }

        int cn = c + stride;
        int nb = (cn < nchunks ? cn : c) * 16;
        ISSUE_EA(nb);
        LDIDX(idxv, nb);

        #pragma unroll
        for (int j = 0; j < 16; j++) { acc[j][0]=0.f; acc[j][1]=0.f; acc[j][2]=0.f; acc[j][3]=0.f; }
        #pragma unroll
        for (int p = 0; p < 4; p++) {
            #pragma unroll
            for (int blk = 0; blk < 16; blk++) {
                uint4 b = W2t[p * 512 + (blk >> 2) * 128 + (blk & 3) * 32];
                mma16(acc[blk], ef[8*p+0], ef[8*p+1], ef[8*p+2], ef[8*p+3], b.x, b.y);
                mma16(acc[blk], ef[8*p+4], ef[8*p+5], ef[8*p+6], ef[8*p+7], b.z, b.w);
            }
        }
        CP_WAIT(1);
        __syncwarp();

        #pragma unroll
        for (int j = 0; j < 16; j++) {
            int cc = j * 8 + 2 * tig;
            float2 sc = *(const float2*)(sScale + cc);
            float2 sh = *(const float2*)(sShift + cc);
            int po = j * 16 + tig * 4;
            float2 r0 = h2f2(*(const unsigned*)(smem + (sPR - sb) + gid * PRB + po));
            float2 q0 = h2f2(*(const unsigned*)(smem + (sPC - sb) + gid * PRB + po));
            float2 r1 = h2f2(*(const unsigned*)(smem + (sPR - sb) + (gid + 8) * PRB + po));
            float2 q1 = h2f2(*(const unsigned*)(smem + (sPC - sb) + (gid + 8) * PRB + po));
            ef[2*j] = f22h2(
                fmaxf(fmaf(acc[j][0] + r0.x + q0.x, sc.x, sh.x), 0.f),
                fmaxf(fmaf(acc[j][1] + r0.y + q0.y, sc.y, sh.y), 0.f));
            ef[2*j+1] = f22h2(
                fmaxf(fmaf(acc[j][2] + r1.x + q1.x, sc.x, sh.x), 0.f),
                fmaxf(fmaf(acc[j][3] + r1.y + q1.y, sc.y, sh.y), 0.f));
        }

        #pragma unroll
        for (int j = 0; j < 16; j++) { acc[j][0]=0.f; acc[j][1]=0.f; acc[j][2]=0.f; acc[j][3]=0.f; }
        #pragma unroll
        for (int p = 0; p < 4; p++) {
            #pragma unroll
            for (int blk = 0; blk < 16; blk++) {
                uint4 b = W3t[p * 512 + (blk >> 2) * 128 + (blk & 3) * 32];
                mma16(acc[blk], ef[8*p+0], ef[8*p+1], ef[8*p+2], ef[8*p+3], b.x, b.y);
                mma16(acc[blk], ef[8*p+4], ef[8*p+5], ef[8*p+6], ef[8*p+7], b.z, b.w);
            }
        }

        {
            int e0 = ebase + gid, e1 = ebase + gid + 8;
            float* po0 = out + (long long)e0 * 128;
            float* po1 = out + (long long)e1 * 128;
            #pragma unroll
            for (int j = 0; j < 16; j++) {
                int cc = j * 8 + 2 * tig;
                float2 bb = *(const float2*)(sB3 + cc);
                if (e0 < E) st_cs_v2(po0 + cc, fmaxf(acc[j][0] + bb.x, 0.f),
                                               fmaxf(acc[j][1] + bb.y, 0.f));
                if (e1 < E) st_cs_v2(po1 + cc, fmaxf(acc[j][2] + bb.x, 0.f),
                                               fmaxf(acc[j][3] + bb.y, 0.f));
            }
        }
    }
    CP_WAIT(0);
}

extern "C" void kernel_launch(void* const* d_in, const int* in_sizes, int n_in,
                              void* d_out, int out_size) {
    const float* x     = (const float*)d_in[0];
    const int*   ei    = (const int*)  d_in[1];
    const float* eattr = (const float*)d_in[2];
    const float* W1    = (const float*)d_in[3];
    const float* b1    = (const float*)d_in[4];
    const float* W2    = (const float*)d_in[5];
    const float* b2    = (const float*)d_in[6];
    const float* gam   = (const float*)d_in[7];
    const float* bet   = (const float*)d_in[8];
    const float* mean  = (const float*)d_in[9];
    const float* var   = (const float*)d_in[10];
    const float* W3    = (const float*)d_in[11];
    const float* b3    = (const float*)d_in[12];
    float* out = (float*)d_out;

    int N = in_sizes[0] / 128;
    int E = in_sizes[2] / 32;
    int nchunks = (E + 15) / 16;
    int ntilesN = (N + 127) / 128;

    cudaFuncSetAttribute(node_proj, cudaFuncAttributeMaxDynamicSharedMemorySize, SMEM_N);
    cudaFuncSetAttribute(edge_kernel, cudaFuncAttributeMaxDynamicSharedMemorySize, SMEM_E);

    node_proj<<<148, 512, SMEM_N>>>(x, W1, W2, W3, N, ntilesN);
    edge_kernel<<<148, NT, SMEM_E>>>(ei, eattr, b1, b2, gam, bet,
                                     mean, var, b3, out, E, nchunks);
}